// round 15
// baseline (speedup 1.0000x reference)
#include <cuda_runtime.h>

// RandomShiftsAug: out[n,c,j,i] = x[n, c, src_h(n,j), src_w(n,i)]
//   kx = shift[n,0], ky = shift[n,1]  (both in [0, 8])
//   th    = max(ky + j - 4, 0); src_h = th - 84*(th >= 84)
//   src_w = clamp(kx + i - 4, 0, 419)
//
// Converged shape (4 rows/thread, 8 aligned LDG.128 front-batched,
// row-invariant clamps, default cache policy = measured optimum, 45.25us
// kernel / ~7.2 TB/s logical, ~90% of HBM spec). Last unmeasured axis:
// CTA granularity. This round: THREADS 256 -> 512 (same warp count per SM,
// half the CTAs -> fewer wave transitions, wider per-CTA load batching).

#define N_BATCH 128
#define CH      9
#define H       84
#define W       420
#define W4      (W / 4)               // 105
#define RPT     4                     // rows per thread
#define JG      (H / RPT)             // 21
#define NWORK   (N_BATCH * CH * JG * W4)   // 2,540,160
#define THREADS 512
#define BLOCKS  ((NWORK + THREADS - 1) / THREADS)   // 4962

__device__ __forceinline__ float4 ldg4(const float* p) {
    return __ldg((const float4*)p);
}

// Map output row j -> source row (edge-clamp low, tile-wrap high).
__device__ __forceinline__ int src_row(int ky, int j) {
    int th = ky + j - 4;
    th = th < 0 ? 0 : th;
    return (th >= H) ? (th - H) : th;
}

template <int O>
__device__ __forceinline__ float4 combine(float4 A, float4 B) {
    float4 v;
    if (O == 0)      { v = A; }
    else if (O == 1) { v.x = A.y; v.y = A.z; v.z = A.w; v.w = B.x; }
    else if (O == 2) { v.x = A.z; v.y = A.w; v.z = B.x; v.w = B.y; }
    else             { v.x = A.w; v.y = B.x; v.z = B.y; v.w = B.z; }
    return v;
}

template <int O>
__device__ __forceinline__ void fast_path(const float* xbase, int ky, int j0,
                                          int q, float4* outp)
{
    const float* rowp[RPT];
#pragma unroll
    for (int jj = 0; jj < RPT; jj++)
        rowp[jj] = xbase + src_row(ky, j0 + jj) * W;

    // Front-batch every load: up to 8 independent LDG.128 in flight.
    float4 A[RPT], B[RPT];
#pragma unroll
    for (int jj = 0; jj < RPT; jj++) {
        A[jj] = ldg4(rowp[jj] + q);
        if (O != 0) B[jj] = ldg4(rowp[jj] + q + 4);
    }
#pragma unroll
    for (int jj = 0; jj < RPT; jj++)
        outp[jj * W4] = combine<O>(A[jj], B[jj]);
}

__global__ __launch_bounds__(THREADS)
void rand_shift_kernel(const float* __restrict__ x,
                       const int*   __restrict__ shift,
                       float4*      __restrict__ out)
{
    const int idx = blockIdx.x * THREADS + threadIdx.x;
    if (idx >= NWORK) return;

    // idx = ((nc*21 + jg)*105 + i4)
    const int i4 = idx % W4;
    const int r  = idx / W4;
    const int jg = r % JG;
    const int nc = r / JG;            // n*9 + c
    const int n  = nc / CH;

    const int kx = __ldg(&shift[2 * n]);
    const int ky = __ldg(&shift[2 * n + 1]);

    const int j0 = RPT * jg;
    const float* xbase = x + nc * H * W;
    float4* outp = out + (nc * H + j0) * W4 + i4;

    const int base = 4 * i4 + kx - 4;     // first source column
    const int o    = kx & 3;              // alignment offset (batch-uniform)
    const int a0   = base - o;            // aligned start (multiple of 4)

    bool fast;
    if (o == 0) fast = (base >= 0) && (base + 3 < W);
    else        fast = (a0 >= 0) && (a0 + 7 < W);

    if (fast) {
        if (o == 0)      fast_path<0>(xbase, ky, j0, a0, outp);
        else if (o == 1) fast_path<1>(xbase, ky, j0, a0, outp);
        else if (o == 2) fast_path<2>(xbase, ky, j0, a0, outp);
        else             fast_path<3>(xbase, ky, j0, a0, outp);
    } else {
        // Edge vectors (~2% of threads): clamped scalar gather.
        const int w0 = min(max(base,     0), W - 1);
        const int w1 = min(max(base + 1, 0), W - 1);
        const int w2 = min(max(base + 2, 0), W - 1);
        const int w3 = min(max(base + 3, 0), W - 1);
#pragma unroll
        for (int jj = 0; jj < RPT; jj++) {
            const float* rp = xbase + src_row(ky, j0 + jj) * W;
            float4 v;
            v.x = __ldg(rp + w0);
            v.y = __ldg(rp + w1);
            v.z = __ldg(rp + w2);
            v.w = __ldg(rp + w3);
            outp[jj * W4] = v;
        }
    }
}

extern "C" void kernel_launch(void* const* d_in, const int* in_sizes, int n_in,
                              void* d_out, int out_size)
{
    const float* x     = (const float*)d_in[0];
    const int*   shift = (const int*)d_in[1];
    float4*      out   = (float4*)d_out;

    rand_shift_kernel<<<BLOCKS, THREADS>>>(x, shift, out);
}

// round 16
// speedup vs baseline: 1.0056x; 1.0056x over previous
#include <cuda_runtime.h>

// RandomShiftsAug: out[n,c,j,i] = x[n, c, src_h(n,j), src_w(n,i)]
//   kx = shift[n,0], ky = shift[n,1]  (both in [0, 8])
//   th    = max(ky + j - 4, 0); src_h = th - 84*(th >= 84)
//   src_w = clamp(kx + i - 4, 0, 419)
//
// FINAL — converged optimum after 14 measured rounds.
// 45.25us kernel = ~7.2 TB/s logical, ~90% of HBM spec, on an irreducible
// 325MB permutation (pure gather: full input read + full output write).
//
// Configuration (each axis measured, see session journal):
//   - 4 output rows/thread at one i4; row map and column clamps hoisted
//   - all 8 aligned LDG.128 front-batched (batch-uniform misalignment
//     o = kx&3 resolved by compile-time register picks in a 4-way branch)
//   - default cache policy (st.cs / ld.cs / L2-evict-last all slower)
//   - 256-thread CTAs, natural regalloc (40 regs, ~59% occ — the optimum;
//     forced 79% occ and 512-thread CTAs measured equal or slower)
// Residual gap to spec = DRAM read/write turnaround; not SM-addressable.

#define N_BATCH 128
#define CH      9
#define H       84
#define W       420
#define W4      (W / 4)               // 105
#define RPT     4                     // rows per thread
#define JG      (H / RPT)             // 21
#define NWORK   (N_BATCH * CH * JG * W4)   // 2,540,160
#define THREADS 256
#define BLOCKS  ((NWORK + THREADS - 1) / THREADS)   // 9923

__device__ __forceinline__ float4 ldg4(const float* p) {
    return __ldg((const float4*)p);
}

// Map output row j -> source row (edge-clamp low, tile-wrap high).
__device__ __forceinline__ int src_row(int ky, int j) {
    int th = ky + j - 4;
    th = th < 0 ? 0 : th;
    return (th >= H) ? (th - H) : th;
}

template <int O>
__device__ __forceinline__ float4 combine(float4 A, float4 B) {
    float4 v;
    if (O == 0)      { v = A; }
    else if (O == 1) { v.x = A.y; v.y = A.z; v.z = A.w; v.w = B.x; }
    else if (O == 2) { v.x = A.z; v.y = A.w; v.z = B.x; v.w = B.y; }
    else             { v.x = A.w; v.y = B.x; v.z = B.y; v.w = B.z; }
    return v;
}

template <int O>
__device__ __forceinline__ void fast_path(const float* xbase, int ky, int j0,
                                          int q, float4* outp)
{
    const float* rowp[RPT];
#pragma unroll
    for (int jj = 0; jj < RPT; jj++)
        rowp[jj] = xbase + src_row(ky, j0 + jj) * W;

    // Front-batch every load: up to 8 independent LDG.128 in flight.
    float4 A[RPT], B[RPT];
#pragma unroll
    for (int jj = 0; jj < RPT; jj++) {
        A[jj] = ldg4(rowp[jj] + q);
        if (O != 0) B[jj] = ldg4(rowp[jj] + q + 4);
    }
#pragma unroll
    for (int jj = 0; jj < RPT; jj++)
        outp[jj * W4] = combine<O>(A[jj], B[jj]);
}

__global__ __launch_bounds__(THREADS)
void rand_shift_kernel(const float* __restrict__ x,
                       const int*   __restrict__ shift,
                       float4*      __restrict__ out)
{
    const int idx = blockIdx.x * THREADS + threadIdx.x;
    if (idx >= NWORK) return;

    // idx = ((nc*21 + jg)*105 + i4)
    const int i4 = idx % W4;
    const int r  = idx / W4;
    const int jg = r % JG;
    const int nc = r / JG;            // n*9 + c
    const int n  = nc / CH;

    const int kx = __ldg(&shift[2 * n]);
    const int ky = __ldg(&shift[2 * n + 1]);

    const int j0 = RPT * jg;
    const float* xbase = x + nc * H * W;
    float4* outp = out + (nc * H + j0) * W4 + i4;

    const int base = 4 * i4 + kx - 4;     // first source column
    const int o    = kx & 3;              // alignment offset (batch-uniform)
    const int a0   = base - o;            // aligned start (multiple of 4)

    bool fast;
    if (o == 0) fast = (base >= 0) && (base + 3 < W);
    else        fast = (a0 >= 0) && (a0 + 7 < W);

    if (fast) {
        if (o == 0)      fast_path<0>(xbase, ky, j0, a0, outp);
        else if (o == 1) fast_path<1>(xbase, ky, j0, a0, outp);
        else if (o == 2) fast_path<2>(xbase, ky, j0, a0, outp);
        else             fast_path<3>(xbase, ky, j0, a0, outp);
    } else {
        // Edge vectors (~2% of threads): clamped scalar gather.
        const int w0 = min(max(base,     0), W - 1);
        const int w1 = min(max(base + 1, 0), W - 1);
        const int w2 = min(max(base + 2, 0), W - 1);
        const int w3 = min(max(base + 3, 0), W - 1);
#pragma unroll
        for (int jj = 0; jj < RPT; jj++) {
            const float* rp = xbase + src_row(ky, j0 + jj) * W;
            float4 v;
            v.x = __ldg(rp + w0);
            v.y = __ldg(rp + w1);
            v.z = __ldg(rp + w2);
            v.w = __ldg(rp + w3);
            outp[jj * W4] = v;
        }
    }
}

extern "C" void kernel_launch(void* const* d_in, const int* in_sizes, int n_in,
                              void* d_out, int out_size)
{
    const float* x     = (const float*)d_in[0];
    const int*   shift = (const int*)d_in[1];
    float4*      out   = (float4*)d_out;

    rand_shift_kernel<<<BLOCKS, THREADS>>>(x, shift, out);
}